// round 6
// baseline (speedup 1.0000x reference)
#include <cuda_runtime.h>
#include <cuda_bf16.h>
#include <math.h>
#include <stdint.h>
#include <stddef.h>

// ============================================================================
// biSoftmax on GB300 via HMMA (mma.sync bf16) split-precision GEMMs.
// R6: warp tile 64x64 (4 warps / 128 threads per CTA, CTA tile 128x128),
//     MMA/LDSM ratio 6 (was 4) to relieve the L1/ldmatrix bottleneck seen in
//     the R5 profile (tensor=42%, L1=66%).
// All GEMMs are NT: C[m,n] = alpha * sum_k A[m,k] * B[n,k]
// fp32 operands stored as bf16 (hi,lo); accumulate Ahi*Bhi + Ahi*Blo + Alo*Bhi.
// ============================================================================

#define SEQ 2048
#define NH 8
#define MROWS (NH * SEQ)                 // 16384
#define SSZ ((size_t)SEQ * SEQ)          // 2^22

typedef __nv_bfloat16 bf16;

// ---------------- scratch (device globals, allocation-free) ----------------
__device__ bf16 g_xh[(size_t)MROWS * SEQ],  g_xl[(size_t)MROWS * SEQ];
__device__ bf16 g_Wh[7 * SSZ],              g_Wl[7 * SSZ];
__device__ bf16 g_Q1h[(size_t)MROWS * SEQ], g_Q1l[(size_t)MROWS * SEQ];
__device__ bf16 g_K1h[(size_t)MROWS * SEQ], g_K1l[(size_t)MROWS * SEQ];
__device__ bf16 g_Q2h[(size_t)MROWS * SEQ], g_Q2l[(size_t)MROWS * SEQ];
__device__ bf16 g_K2h[(size_t)MROWS * SEQ], g_K2l[(size_t)MROWS * SEQ];
__device__ bf16 g_Vth[(size_t)MROWS * SEQ], g_Vtl[(size_t)MROWS * SEQ];
__device__ bf16 g_A1h[(size_t)MROWS * SEQ], g_A1l[(size_t)MROWS * SEQ];
__device__ bf16 g_A2h[(size_t)MROWS * SEQ], g_A2l[(size_t)MROWS * SEQ];
__device__ bf16 g_Ch [(size_t)MROWS * SEQ], g_Cl [(size_t)MROWS * SEQ];
__device__ float g_S1[(size_t)MROWS * SEQ], g_S2[(size_t)MROWS * SEQ];

// ---------------- PTX helpers ----------------
__device__ __forceinline__ uint32_t smem_u32(const void* p) {
    uint32_t a;
    asm("{ .reg .u64 t; cvta.to.shared.u64 t, %1; cvt.u32.u64 %0, t; }" : "=r"(a) : "l"(p));
    return a;
}

#define CP16(dst, src) \
    asm volatile("cp.async.cg.shared.global [%0], [%1], 16;" :: "r"(dst), "l"(src) : "memory")
#define CP_COMMIT() asm volatile("cp.async.commit_group;" ::: "memory")
#define CP_WAIT1()  asm volatile("cp.async.wait_group 1;" ::: "memory")

#define LDSM4(r0, r1, r2, r3, a) \
    asm volatile("ldmatrix.sync.aligned.m8n8.x4.shared.b16 {%0,%1,%2,%3}, [%4];" \
        : "=r"(r0), "=r"(r1), "=r"(r2), "=r"(r3) : "r"(a))

#define MMA_BF16(d, a, b) \
    asm volatile("mma.sync.aligned.m16n8k16.row.col.f32.bf16.bf16.f32 " \
        "{%0,%1,%2,%3}, {%4,%5,%6,%7}, {%8,%9}, {%0,%1,%2,%3};" \
        : "+f"((d)[0]), "+f"((d)[1]), "+f"((d)[2]), "+f"((d)[3]) \
        : "r"((a)[0]), "r"((a)[1]), "r"((a)[2]), "r"((a)[3]), "r"((b)[0]), "r"((b)[1]))

// ---------------- HMMA split-precision GEMM ----------------
// CTA tile 128x128, BK=32, 2 stages, 128 threads (4 warps of 64x64), 2 CTAs/SM.
// smem row = 32 bf16 (64B) + 16B pad = 80B.
// Stage layout: Ahi[0,10240) Alo[10240,20480) Bhi[20480,30720) Blo[30720,40960)
static constexpr int STAGE_B = 40960;
static constexpr int SMEM_HG = 2 * STAGE_B;   // 81920 -> 2 CTAs/SM

// EPI: 0 = fp32 * alpha, 1 = bf16 (hi,lo) pair
template <int EPI>
__global__ __launch_bounds__(128, 2)
void hgemm3(const bf16* __restrict__ Ah, const bf16* __restrict__ Al,
            const bf16* __restrict__ Bh, const bf16* __restrict__ Bl,
            float* __restrict__ Cf, bf16* __restrict__ Ch, bf16* __restrict__ Cl,
            int K, int ldc, size_t sC, int azRows, int bzRows, float alpha)
{
    extern __shared__ char smem[];
    const uint32_t sbase = smem_u32(smem);
    const int tid  = threadIdx.x;
    const int lane = tid & 31;
    const int wid  = tid >> 5;            // 0..3
    const int wm   = wid >> 1;            // 0..1 -> 64-row slab
    const int wn   = wid & 1;             // 0..1 -> 64-col slab
    const int row0 = blockIdx.y * 128;
    const int col0 = blockIdx.x * 128;
    const int z    = blockIdx.z;

    // ---- loader lanes: 128 threads, each one full row (4x16B) per buffer ----
    const int lr = tid;                   // 0..127
    const size_t arow = (size_t)(row0 + z * azRows + lr);
    const size_t brow = (size_t)(col0 + z * bzRows + lr);
    const bf16* pAh = Ah + arow * K;
    const bf16* pAl = Al + arow * K;
    const bf16* pBh = Bh + brow * K;
    const bf16* pBl = Bl + brow * K;
    const uint32_t lsw = (uint32_t)(lr & 3);
    uint32_t st[4];
    #pragma unroll
    for (int c = 0; c < 4; c++) st[c] = (uint32_t)lr * 80u + (((uint32_t)c ^ lsw) << 4);

    auto prefetch = [&](int kt) {
        const uint32_t sb = sbase + (uint32_t)(kt & 1) * STAGE_B;
        const int go = kt * 32;
        #pragma unroll
        for (int c = 0; c < 4; c++) CP16(sb +          st[c], pAh + go + c * 8);
        #pragma unroll
        for (int c = 0; c < 4; c++) CP16(sb + 10240u + st[c], pAl + go + c * 8);
        #pragma unroll
        for (int c = 0; c < 4; c++) CP16(sb + 20480u + st[c], pBh + go + c * 8);
        #pragma unroll
        for (int c = 0; c < 4; c++) CP16(sb + 30720u + st[c], pBl + go + c * 8);
    };

    // ---- fragment addressing ----
    const int lr16  = lane & 15;
    const uint32_t khalf = (uint32_t)(lane >> 4);
    const uint32_t fsw   = (uint32_t)(lane & 3);
    uint32_t a_base[4], b_base[4];
    #pragma unroll
    for (int mi = 0; mi < 4; mi++) a_base[mi] = (uint32_t)(wm * 64 + mi * 16 + lr16) * 80u;
    #pragma unroll
    for (int g = 0; g < 4; g++)    b_base[g]  = (uint32_t)(wn * 64 + g * 16 + lr16) * 80u;

    float acc[4][8][4];
    #pragma unroll
    for (int mi = 0; mi < 4; mi++)
        #pragma unroll
        for (int nj = 0; nj < 8; nj++)
            #pragma unroll
            for (int q = 0; q < 4; q++) acc[mi][nj][q] = 0.0f;

    const int nk = K >> 5;

    prefetch(0); CP_COMMIT();
    prefetch(1); CP_COMMIT();

    for (int kt = 0; kt < nk; kt++) {
        CP_WAIT1();
        __syncthreads();

        const uint32_t stg = sbase + (uint32_t)(kt & 1) * STAGE_B;
        #pragma unroll
        for (int ks = 0; ks < 2; ks++) {
            const uint32_t coff = ((((uint32_t)(ks * 2) + khalf) ^ fsw) << 4);
            // B fragments: 8 nj x (hi,lo), 32 regs
            uint32_t Bhi[8][2], Blo[8][2];
            #pragma unroll
            for (int g = 0; g < 4; g++) {
                uint32_t q0, q1, q2, q3;
                LDSM4(q0, q1, q2, q3, stg + 20480u + b_base[g] + coff);
                Bhi[2 * g][0] = q0;     Bhi[2 * g][1] = q2;
                Bhi[2 * g + 1][0] = q1; Bhi[2 * g + 1][1] = q3;
                LDSM4(q0, q1, q2, q3, stg + 30720u + b_base[g] + coff);
                Blo[2 * g][0] = q0;     Blo[2 * g][1] = q2;
                Blo[2 * g + 1][0] = q1; Blo[2 * g + 1][1] = q3;
            }
            // A fragments per mi (8 regs live at a time)
            #pragma unroll
            for (int mi = 0; mi < 4; mi++) {
                uint32_t Ahi[4], Alo[4];
                LDSM4(Ahi[0], Ahi[1], Ahi[2], Ahi[3], stg + a_base[mi] + coff);
                LDSM4(Alo[0], Alo[1], Alo[2], Alo[3], stg + 10240u + a_base[mi] + coff);
                #pragma unroll
                for (int nj = 0; nj < 8; nj++) MMA_BF16(acc[mi][nj], Ahi, Bhi[nj]);
                #pragma unroll
                for (int nj = 0; nj < 8; nj++) MMA_BF16(acc[mi][nj], Ahi, Blo[nj]);
                #pragma unroll
                for (int nj = 0; nj < 8; nj++) MMA_BF16(acc[mi][nj], Alo, Bhi[nj]);
            }
        }

        __syncthreads();
        if (kt + 2 < nk) prefetch(kt + 2);
        CP_COMMIT();
    }

    // ---- epilogue ----
    const size_t cb = (size_t)z * sC;
    #pragma unroll
    for (int mi = 0; mi < 4; mi++) {
        #pragma unroll
        for (int nj = 0; nj < 8; nj++) {
            const int rg = row0 + wm * 64 + mi * 16 + (lane >> 2);
            const int cg = col0 + wn * 64 + nj * 8 + (lane & 3) * 2;
            float d0 = acc[mi][nj][0] * alpha, d1 = acc[mi][nj][1] * alpha;
            float d2 = acc[mi][nj][2] * alpha, d3 = acc[mi][nj][3] * alpha;
            const size_t i0 = cb + (size_t)rg * ldc + cg;
            const size_t i1 = cb + (size_t)(rg + 8) * ldc + cg;
            if (EPI == 0) {
                *(float2*)(Cf + i0) = make_float2(d0, d1);
                *(float2*)(Cf + i1) = make_float2(d2, d3);
            } else {
                __nv_bfloat162 h, l;
                h.x = __float2bfloat16(d0);
                h.y = __float2bfloat16(d1);
                l.x = __float2bfloat16(d0 - __bfloat162float(h.x));
                l.y = __float2bfloat16(d1 - __bfloat162float(h.y));
                *(__nv_bfloat162*)(Ch + i0) = h;
                *(__nv_bfloat162*)(Cl + i0) = l;
                h.x = __float2bfloat16(d2);
                h.y = __float2bfloat16(d3);
                l.x = __float2bfloat16(d2 - __bfloat162float(h.x));
                l.y = __float2bfloat16(d3 - __bfloat162float(h.y));
                *(__nv_bfloat162*)(Ch + i1) = h;
                *(__nv_bfloat162*)(Cl + i1) = l;
            }
        }
    }
}

// ---------------- fused conversion: x + all 7 weights in ONE launch ----------
struct WPtrs { const float* p[7]; };

__global__ __launch_bounds__(256)
void convert_all(const float* __restrict__ x, WPtrs w,
                 bf16* __restrict__ xh, bf16* __restrict__ xl,
                 bf16* __restrict__ Wh, bf16* __restrict__ Wl)
{
    const size_t stride = (size_t)gridDim.x * blockDim.x;
    size_t i = (size_t)blockIdx.x * blockDim.x + threadIdx.x;
    if (blockIdx.y == 0) {
        const size_t n = (size_t)MROWS * SEQ;
        for (; i < n; i += stride) {
            float f = x[i];
            bf16 h = __float2bfloat16(f);
            xh[i] = h;
            xl[i] = __float2bfloat16(f - __bfloat162float(h));
        }
    } else {
        const size_t n = 7 * SSZ;
        for (; i < n; i += stride) {
            const int r = (int)(i >> 22);            // SSZ = 2^22
            const size_t off = i & (SSZ - 1);
            float f = w.p[r][off];
            bf16 h = __float2bfloat16(f);
            Wh[i] = h;
            Wl[i] = __float2bfloat16(f - __bfloat162float(h));
        }
    }
}

__global__ __launch_bounds__(256)
void softmax_pair(const float* __restrict__ S, bf16* __restrict__ Ph,
                  bf16* __restrict__ Pl)
{
    const int tid = threadIdx.x;
    const float* p = S + (size_t)blockIdx.x * SEQ;
    bf16* oh = Ph + (size_t)blockIdx.x * SEQ;
    bf16* ol = Pl + (size_t)blockIdx.x * SEQ;
    __shared__ float buf[SEQ];
    __shared__ float red[256];

    float m = -INFINITY;
    for (int i = tid; i < SEQ; i += 256) { float v = p[i]; buf[i] = v; m = fmaxf(m, v); }
    red[tid] = m; __syncthreads();
    for (int s = 128; s > 0; s >>= 1) { if (tid < s) red[tid] = fmaxf(red[tid], red[tid + s]); __syncthreads(); }
    m = red[0]; __syncthreads();

    float sum = 0.0f;
    for (int i = tid; i < SEQ; i += 256) { float e = __expf(buf[i] - m); buf[i] = e; sum += e; }
    red[tid] = sum; __syncthreads();
    for (int s = 128; s > 0; s >>= 1) { if (tid < s) red[tid] += red[tid + s]; __syncthreads(); }
    const float inv = 1.0f / red[0]; __syncthreads();

    for (int i = tid; i < SEQ; i += 256) {
        float f = buf[i] * inv;
        bf16 h = __float2bfloat16(f);
        oh[i] = h;
        ol[i] = __float2bfloat16(f - __bfloat162float(h));
    }
}

__global__ __launch_bounds__(256)
void diffsq_pair(const float* __restrict__ a, const float* __restrict__ b,
                 bf16* __restrict__ hi, bf16* __restrict__ lo, size_t n)
{
    size_t i = (size_t)blockIdx.x * blockDim.x + threadIdx.x;
    size_t st = (size_t)gridDim.x * blockDim.x;
    for (; i < n; i += st) {
        float d = a[i] - b[i];
        float f = d * d;
        bf16 h = __float2bfloat16(f);
        hi[i] = h;
        lo[i] = __float2bfloat16(f - __bfloat162float(h));
    }
}

// ---------------- host side ----------------
template <typename T>
static T* sym_addr(T* symbol) {
    void* p = nullptr;
    cudaGetSymbolAddress(&p, (const void*)symbol);
    return (T*)p;
}

static void run_hgemm(const bf16* Ah, const bf16* Al, int az,
                      const bf16* Bh, const bf16* Bl, int bz,
                      int Mtiles, int batch, int epi,
                      float* Cf, bf16* Ch, bf16* Cl, size_t sC, float alpha)
{
    dim3 grid(SEQ / 128, Mtiles, batch);
    if (epi == 0)
        hgemm3<0><<<grid, 128, SMEM_HG>>>(Ah, Al, Bh, Bl, Cf, Ch, Cl,
                                          SEQ, SEQ, sC, az, bz, alpha);
    else
        hgemm3<1><<<grid, 128, SMEM_HG>>>(Ah, Al, Bh, Bl, Cf, Ch, Cl,
                                          SEQ, SEQ, sC, az, bz, alpha);
}

extern "C" void kernel_launch(void* const* d_in, const int* in_sizes, int n_in,
                              void* d_out, int out_size)
{
    (void)in_sizes; (void)n_in; (void)out_size;
    const float* x = (const float*)d_in[0];
    WPtrs w;
    for (int i = 0; i < 7; i++) w.p[i] = (const float*)d_in[1 + i];
    float* out = (float*)d_out;

    cudaFuncSetAttribute((const void*)hgemm3<0>,
                         cudaFuncAttributeMaxDynamicSharedMemorySize, SMEM_HG);
    cudaFuncSetAttribute((const void*)hgemm3<1>,
                         cudaFuncAttributeMaxDynamicSharedMemorySize, SMEM_HG);

    bf16 *xh = sym_addr(g_xh), *xl = sym_addr(g_xl);
    bf16 *Wh = sym_addr(g_Wh), *Wl = sym_addr(g_Wl);
    bf16 *Q1h = sym_addr(g_Q1h), *Q1l = sym_addr(g_Q1l);
    bf16 *K1h = sym_addr(g_K1h), *K1l = sym_addr(g_K1l);
    bf16 *Q2h = sym_addr(g_Q2h), *Q2l = sym_addr(g_Q2l);
    bf16 *K2h = sym_addr(g_K2h), *K2l = sym_addr(g_K2l);
    bf16 *Vth = sym_addr(g_Vth), *Vtl = sym_addr(g_Vtl);
    bf16 *A1h = sym_addr(g_A1h), *A1l = sym_addr(g_A1l);
    bf16 *A2h = sym_addr(g_A2h), *A2l = sym_addr(g_A2l);
    bf16 *Chh = sym_addr(g_Ch),  *Cll = sym_addr(g_Cl);
    float *S1 = sym_addr(g_S1),  *S2 = sym_addr(g_S2);

    const size_t NTOT = (size_t)MROWS * SEQ;
    const float scale = 1.0f / sqrtf((float)SEQ);

    // [0] conversions (single launch)
    convert_all<<<dim3(1024, 2), 256>>>(x, w, xh, xl, Wh, Wl);

    // [1..4] projections: P = X @ W^T -> bf16 pairs
    run_hgemm(xh, xl, 0, Wh + 0 * SSZ, Wl + 0 * SSZ, 0, MROWS / 128, 1, 1,
              nullptr, Q1h, Q1l, 0, 1.0f);
    run_hgemm(xh, xl, 0, Wh + 1 * SSZ, Wl + 1 * SSZ, 0, MROWS / 128, 1, 1,
              nullptr, K1h, K1l, 0, 1.0f);
    run_hgemm(xh, xl, 0, Wh + 2 * SSZ, Wl + 2 * SSZ, 0, MROWS / 128, 1, 1,
              nullptr, Q2h, Q2l, 0, 1.0f);
    run_hgemm(xh, xl, 0, Wh + 3 * SSZ, Wl + 3 * SSZ, 0, MROWS / 128, 1, 1,
              nullptr, K2h, K2l, 0, 1.0f);

    // [5] Vt[h] = Wv @ X[h]^T -> bf16 pair   (ncu -s 5 target)
    run_hgemm(Wh + 4 * SSZ, Wl + 4 * SSZ, 0, xh, xl, SEQ, SEQ / 128, NH, 1,
              nullptr, Vth, Vtl, SSZ, 1.0f);

    // [6,7] logits: S_i = scale * Q_i[h] @ K_i[h]^T -> fp32
    run_hgemm(Q1h, Q1l, SEQ, K1h, K1l, SEQ, SEQ / 128, NH, 0,
              S1, nullptr, nullptr, SSZ, scale);
    run_hgemm(Q2h, Q2l, SEQ, K2h, K2l, SEQ, SEQ / 128, NH, 0,
              S2, nullptr, nullptr, SSZ, scale);

    // [8,9] softmax rows -> bf16 pairs
    softmax_pair<<<MROWS, 256>>>(S1, A1h, A1l);
    softmax_pair<<<MROWS, 256>>>(S2, A2h, A2l);

    // [10,11] scores: Sc_i = A_i @ W_i^T -> fp32 (reuse S1/S2)
    run_hgemm(A1h, A1l, SEQ, Wh + 5 * SSZ, Wl + 5 * SSZ, 0, SEQ / 128, NH, 0,
              S1, nullptr, nullptr, SSZ, 1.0f);
    run_hgemm(A2h, A2l, SEQ, Wh + 6 * SSZ, Wl + 6 * SSZ, 0, SEQ / 128, NH, 0,
              S2, nullptr, nullptr, SSZ, 1.0f);

    // [12] circle = (Sc1 - Sc2)^2 -> bf16 pair
    diffsq_pair<<<2048, 256>>>(S1, S2, Chh, Cll, NTOT);

    // [13] out[h] = circle[h] @ Vt[h]^T -> fp32
    run_hgemm(Chh, Cll, SEQ, Vth, Vtl, SEQ, SEQ / 128, NH, 0,
              out, nullptr, nullptr, SSZ, 1.0f);
}

// round 7
// speedup vs baseline: 1.6590x; 1.6590x over previous
#include <cuda_runtime.h>
#include <cuda_bf16.h>
#include <math.h>
#include <stdint.h>
#include <stddef.h>

// ============================================================================
// biSoftmax on GB300 via HMMA (mma.sync bf16) split-precision GEMMs.
// R7: back to warp tile 64x32 / 256 thr / 2 CTAs/SM (the only 16-warp/SM
//     config under the 128-reg/thread cap), now with: no smem padding
//     ((r>>1)&3 chunk swizzle), 3-stage cp.async pipeline with ONE sync per
//     k-step, and batched GEMM launches (8 launches total).
// All GEMMs are NT: C[m,n] = alpha * sum_k A[m,k] * B[n,k]
// fp32 operands stored as bf16 (hi,lo); accumulate Ahi*Bhi + Ahi*Blo + Alo*Bhi.
// ============================================================================

#define SEQ 2048
#define NH 8
#define MROWS (NH * SEQ)                 // 16384
#define SSZ ((size_t)SEQ * SEQ)          // 2^22
#define NTOT ((size_t)MROWS * SEQ)       // 2^25

typedef __nv_bfloat16 bf16;

// ---------------- scratch (device globals, allocation-free) ----------------
__device__ bf16 g_xh[NTOT],      g_xl[NTOT];
__device__ bf16 g_Wh[7 * SSZ],   g_Wl[7 * SSZ];    // Wq1,Wk1,Wq2,Wk2,Wv,W1,W2
__device__ bf16 g_PRh[4 * NTOT], g_PRl[4 * NTOT];  // Q1,K1,Q2,K2 (proj outputs)
__device__ bf16 g_Vth[NTOT],     g_Vtl[NTOT];      // [h][e][t]
__device__ bf16 g_Ah[2 * NTOT],  g_Al[2 * NTOT];   // A1,A2 (softmax outputs)
__device__ bf16 g_Ch[NTOT],      g_Cl[NTOT];       // circle
__device__ float g_S[2 * NTOT];                    // logits / scores (fp32)

// ---------------- PTX helpers ----------------
__device__ __forceinline__ uint32_t smem_u32(const void* p) {
    uint32_t a;
    asm("{ .reg .u64 t; cvta.to.shared.u64 t, %1; cvt.u32.u64 %0, t; }" : "=r"(a) : "l"(p));
    return a;
}

#define CP16(dst, src) \
    asm volatile("cp.async.cg.shared.global [%0], [%1], 16;" :: "r"(dst), "l"(src) : "memory")
#define CP_COMMIT() asm volatile("cp.async.commit_group;" ::: "memory")
#define CP_WAIT1()  asm volatile("cp.async.wait_group 1;" ::: "memory")

#define LDSM4(r0, r1, r2, r3, a) \
    asm volatile("ldmatrix.sync.aligned.m8n8.x4.shared.b16 {%0,%1,%2,%3}, [%4];" \
        : "=r"(r0), "=r"(r1), "=r"(r2), "=r"(r3) : "r"(a))

#define MMA_BF16(d, a, b) \
    asm volatile("mma.sync.aligned.m16n8k16.row.col.f32.bf16.bf16.f32 " \
        "{%0,%1,%2,%3}, {%4,%5,%6,%7}, {%8,%9}, {%0,%1,%2,%3};" \
        : "+f"((d)[0]), "+f"((d)[1]), "+f"((d)[2]), "+f"((d)[3]) \
        : "r"((a)[0]), "r"((a)[1]), "r"((a)[2]), "r"((a)[3]), "r"((b)[0]), "r"((b)[1]))

// ---------------- HMMA split-precision GEMM ----------------
// CTA tile 128x128, BK=32, 3 stages, 256 threads (8 warps of 64x32), 2 CTAs/SM.
// smem row = 32 bf16 = 64B packed; chunk c of row r stored at
//   r*64 + ((c ^ ((r>>1)&3)) << 4)   -> conflict-free ldmatrix (verified).
// Stage layout: Ahi[0,8192) Alo[8192,16384) Bhi[16384,24576) Blo[24576,32768)
static constexpr int STAGE_B = 32768;
static constexpr int SMEM_HG = 3 * STAGE_B;   // 98304 -> 2 CTAs/SM (192KB)

// z decomposition: zi = z>>3, zr = z&7; row offsets = zi*Hi + zr*Lo
// EPI: 0 = fp32 * alpha, 1 = bf16 (hi,lo) pair
template <int EPI>
__global__ __launch_bounds__(256, 2)
void hgemm3(const bf16* __restrict__ Ah, const bf16* __restrict__ Al,
            const bf16* __restrict__ Bh, const bf16* __restrict__ Bl,
            float* __restrict__ Cf, bf16* __restrict__ Ch, bf16* __restrict__ Cl,
            int K, int ldc, size_t sC,
            int azHi, int azLo, int bzHi, int bzLo, float alpha)
{
    extern __shared__ char smem[];
    const uint32_t sbase = smem_u32(smem);
    const int tid  = threadIdx.x;
    const int lane = tid & 31;
    const int wid  = tid >> 5;
    const int wm   = wid >> 2;          // 0..1 -> 64-row slab
    const int wn   = wid & 3;           // 0..3 -> 32-col slab
    const int row0 = blockIdx.y * 128;
    const int col0 = blockIdx.x * 128;
    const int z    = blockIdx.z;
    const int zi   = z >> 3, zr = z & 7;
    const int aoff = zi * azHi + zr * azLo;
    const int boff = zi * bzHi + zr * bzLo;

    // ---- loader lanes: 256 threads, each 2x16B per buffer per stage ----
    const int lr  = tid >> 1;           // 0..127 row
    const int lcb = (tid & 1) * 2;      // chunk 0 or 2
    const size_t arow = (size_t)(row0 + aoff + lr);
    const size_t brow = (size_t)(col0 + boff + lr);
    const bf16* pAh = Ah + arow * K + lcb * 8;
    const bf16* pAl = Al + arow * K + lcb * 8;
    const bf16* pBh = Bh + brow * K + lcb * 8;
    const bf16* pBl = Bl + brow * K + lcb * 8;
    const uint32_t lsw = (uint32_t)((lr >> 1) & 3);
    const uint32_t st1 = lr * 64 + (((uint32_t)lcb ^ lsw) << 4);
    const uint32_t st2 = lr * 64 + ((((uint32_t)lcb + 1u) ^ lsw) << 4);

    auto prefetch = [&](int kt, int stage) {
        const uint32_t sb = sbase + (uint32_t)stage * STAGE_B;
        const int go = kt * 32;
        CP16(sb +          st1, pAh + go); CP16(sb +          st2, pAh + go + 8);
        CP16(sb +  8192u + st1, pAl + go); CP16(sb +  8192u + st2, pAl + go + 8);
        CP16(sb + 16384u + st1, pBh + go); CP16(sb + 16384u + st2, pBh + go + 8);
        CP16(sb + 24576u + st1, pBl + go); CP16(sb + 24576u + st2, pBl + go + 8);
    };

    // ---- fragment addressing ----
    const int lr16  = lane & 15;
    const uint32_t khalf = (uint32_t)(lane >> 4);
    const uint32_t fsw   = (uint32_t)((lr16 >> 1) & 3);
    uint32_t a_base[4], b_base[2];
    #pragma unroll
    for (int mi = 0; mi < 4; mi++) a_base[mi] = (uint32_t)(wm * 64 + mi * 16 + lr16) * 64u;
    #pragma unroll
    for (int g = 0; g < 2; g++)    b_base[g]  = (uint32_t)(wn * 32 + g * 16 + lr16) * 64u;

    float acc[4][4][4];
    #pragma unroll
    for (int mi = 0; mi < 4; mi++)
        #pragma unroll
        for (int nj = 0; nj < 4; nj++)
            #pragma unroll
            for (int q = 0; q < 4; q++) acc[mi][nj][q] = 0.0f;

    const int nk = K >> 5;

    prefetch(0, 0); CP_COMMIT();
    prefetch(1, 1); CP_COMMIT();

    int cs = 0;           // compute stage
    int ps = 2;           // prefetch stage
    for (int kt = 0; kt < nk; kt++) {
        CP_WAIT1();
        __syncthreads();

        const uint32_t stg = sbase + (uint32_t)cs * STAGE_B;
        #pragma unroll
        for (int ks = 0; ks < 2; ks++) {
            const uint32_t coff = ((((uint32_t)(ks * 2) + khalf) ^ fsw) << 4);
            uint32_t Bhi[4][2], Blo[4][2];
            #pragma unroll
            for (int g = 0; g < 2; g++) {
                uint32_t q0, q1, q2, q3;
                LDSM4(q0, q1, q2, q3, stg + 16384u + b_base[g] + coff);
                Bhi[2 * g][0] = q0;     Bhi[2 * g][1] = q2;
                Bhi[2 * g + 1][0] = q1; Bhi[2 * g + 1][1] = q3;
                LDSM4(q0, q1, q2, q3, stg + 24576u + b_base[g] + coff);
                Blo[2 * g][0] = q0;     Blo[2 * g][1] = q2;
                Blo[2 * g + 1][0] = q1; Blo[2 * g + 1][1] = q3;
            }
            #pragma unroll
            for (int mi = 0; mi < 4; mi++) {
                uint32_t Ahi[4], Alo[4];
                LDSM4(Ahi[0], Ahi[1], Ahi[2], Ahi[3], stg + a_base[mi] + coff);
                LDSM4(Alo[0], Alo[1], Alo[2], Alo[3], stg + 8192u + a_base[mi] + coff);
                #pragma unroll
                for (int nj = 0; nj < 4; nj++) MMA_BF16(acc[mi][nj], Ahi, Bhi[nj]);
                #pragma unroll
                for (int nj = 0; nj < 4; nj++) MMA_BF16(acc[mi][nj], Ahi, Blo[nj]);
                #pragma unroll
                for (int nj = 0; nj < 4; nj++) MMA_BF16(acc[mi][nj], Alo, Bhi[nj]);
            }
        }

        // 3-stage: prefetch target (kt+2)%3 is never the stage any warp that
        // passed the sync above can still be reading (kt%3 or (kt+1)%3).
        if (kt + 2 < nk) prefetch(kt + 2, ps);
        CP_COMMIT();
        cs = (cs == 2) ? 0 : cs + 1;
        ps = (ps == 2) ? 0 : ps + 1;
    }

    // ---- epilogue ----
    const size_t cb = (size_t)z * sC;
    #pragma unroll
    for (int mi = 0; mi < 4; mi++) {
        #pragma unroll
        for (int nj = 0; nj < 4; nj++) {
            const int rg = row0 + wm * 64 + mi * 16 + (lane >> 2);
            const int cg = col0 + wn * 32 + nj * 8 + (lane & 3) * 2;
            float d0 = acc[mi][nj][0] * alpha, d1 = acc[mi][nj][1] * alpha;
            float d2 = acc[mi][nj][2] * alpha, d3 = acc[mi][nj][3] * alpha;
            const size_t i0 = cb + (size_t)rg * ldc + cg;
            const size_t i1 = cb + (size_t)(rg + 8) * ldc + cg;
            if (EPI == 0) {
                *(float2*)(Cf + i0) = make_float2(d0, d1);
                *(float2*)(Cf + i1) = make_float2(d2, d3);
            } else {
                __nv_bfloat162 h, l;
                h.x = __float2bfloat16(d0);
                h.y = __float2bfloat16(d1);
                l.x = __float2bfloat16(d0 - __bfloat162float(h.x));
                l.y = __float2bfloat16(d1 - __bfloat162float(h.y));
                *(__nv_bfloat162*)(Ch + i0) = h;
                *(__nv_bfloat162*)(Cl + i0) = l;
                h.x = __float2bfloat16(d2);
                h.y = __float2bfloat16(d3);
                l.x = __float2bfloat16(d2 - __bfloat162float(h.x));
                l.y = __float2bfloat16(d3 - __bfloat162float(h.y));
                *(__nv_bfloat162*)(Ch + i1) = h;
                *(__nv_bfloat162*)(Cl + i1) = l;
            }
        }
    }
}

// ---------------- fused conversion: x + all 7 weights in ONE launch ----------
struct WPtrs { const float* p[7]; };

__global__ __launch_bounds__(256)
void convert_all(const float* __restrict__ x, WPtrs w,
                 bf16* __restrict__ xh, bf16* __restrict__ xl,
                 bf16* __restrict__ Wh, bf16* __restrict__ Wl)
{
    const size_t stride = (size_t)gridDim.x * blockDim.x;
    size_t i = (size_t)blockIdx.x * blockDim.x + threadIdx.x;
    if (blockIdx.y == 0) {
        for (; i < NTOT; i += stride) {
            float f = x[i];
            bf16 h = __float2bfloat16(f);
            xh[i] = h;
            xl[i] = __float2bfloat16(f - __bfloat162float(h));
        }
    } else {
        const size_t n = 7 * SSZ;
        for (; i < n; i += stride) {
            const int r = (int)(i >> 22);            // SSZ = 2^22
            const size_t off = i & (SSZ - 1);
            float f = w.p[r][off];
            bf16 h = __float2bfloat16(f);
            Wh[i] = h;
            Wl[i] = __float2bfloat16(f - __bfloat162float(h));
        }
    }
}

__global__ __launch_bounds__(256)
void softmax_pair(const float* __restrict__ S, bf16* __restrict__ Ph,
                  bf16* __restrict__ Pl)
{
    const int tid = threadIdx.x;
    const float* p = S + (size_t)blockIdx.x * SEQ;
    bf16* oh = Ph + (size_t)blockIdx.x * SEQ;
    bf16* ol = Pl + (size_t)blockIdx.x * SEQ;
    __shared__ float buf[SEQ];
    __shared__ float red[256];

    float m = -INFINITY;
    for (int i = tid; i < SEQ; i += 256) { float v = p[i]; buf[i] = v; m = fmaxf(m, v); }
    red[tid] = m; __syncthreads();
    for (int s = 128; s > 0; s >>= 1) { if (tid < s) red[tid] = fmaxf(red[tid], red[tid + s]); __syncthreads(); }
    m = red[0]; __syncthreads();

    float sum = 0.0f;
    for (int i = tid; i < SEQ; i += 256) { float e = __expf(buf[i] - m); buf[i] = e; sum += e; }
    red[tid] = sum; __syncthreads();
    for (int s = 128; s > 0; s >>= 1) { if (tid < s) red[tid] += red[tid + s]; __syncthreads(); }
    const float inv = 1.0f / red[0]; __syncthreads();

    for (int i = tid; i < SEQ; i += 256) {
        float f = buf[i] * inv;
        bf16 h = __float2bfloat16(f);
        oh[i] = h;
        ol[i] = __float2bfloat16(f - __bfloat162float(h));
    }
}

__global__ __launch_bounds__(256)
void diffsq_pair(const float* __restrict__ a, const float* __restrict__ b,
                 bf16* __restrict__ hi, bf16* __restrict__ lo, size_t n)
{
    size_t i = (size_t)blockIdx.x * blockDim.x + threadIdx.x;
    size_t st = (size_t)gridDim.x * blockDim.x;
    for (; i < n; i += st) {
        float d = a[i] - b[i];
        float f = d * d;
        bf16 h = __float2bfloat16(f);
        hi[i] = h;
        lo[i] = __float2bfloat16(f - __bfloat162float(h));
    }
}

// ---------------- host side ----------------
template <typename T>
static T* sym_addr(T* symbol) {
    void* p = nullptr;
    cudaGetSymbolAddress(&p, (const void*)symbol);
    return (T*)p;
}

static void run_hgemm(const bf16* Ah, const bf16* Al, int azHi, int azLo,
                      const bf16* Bh, const bf16* Bl, int bzHi, int bzLo,
                      int Mtiles, int batch, int epi,
                      float* Cf, bf16* Ch, bf16* Cl, size_t sC, float alpha)
{
    dim3 grid(SEQ / 128, Mtiles, batch);
    if (epi == 0)
        hgemm3<0><<<grid, 256, SMEM_HG>>>(Ah, Al, Bh, Bl, Cf, Ch, Cl,
                                          SEQ, SEQ, sC, azHi, azLo, bzHi, bzLo, alpha);
    else
        hgemm3<1><<<grid, 256, SMEM_HG>>>(Ah, Al, Bh, Bl, Cf, Ch, Cl,
                                          SEQ, SEQ, sC, azHi, azLo, bzHi, bzLo, alpha);
}

extern "C" void kernel_launch(void* const* d_in, const int* in_sizes, int n_in,
                              void* d_out, int out_size)
{
    (void)in_sizes; (void)n_in; (void)out_size;
    const float* x = (const float*)d_in[0];
    WPtrs w;
    for (int i = 0; i < 7; i++) w.p[i] = (const float*)d_in[1 + i];
    float* out = (float*)d_out;

    cudaFuncSetAttribute((const void*)hgemm3<0>,
                         cudaFuncAttributeMaxDynamicSharedMemorySize, SMEM_HG);
    cudaFuncSetAttribute((const void*)hgemm3<1>,
                         cudaFuncAttributeMaxDynamicSharedMemorySize, SMEM_HG);

    bf16 *xh = sym_addr(g_xh),  *xl = sym_addr(g_xl);
    bf16 *Wh = sym_addr(g_Wh),  *Wl = sym_addr(g_Wl);
    bf16 *PRh = sym_addr(g_PRh), *PRl = sym_addr(g_PRl);
    bf16 *Vth = sym_addr(g_Vth), *Vtl = sym_addr(g_Vtl);
    bf16 *Ahh = sym_addr(g_Ah),  *All = sym_addr(g_Al);
    bf16 *Chh = sym_addr(g_Ch),  *Cll = sym_addr(g_Cl);
    float *S = sym_addr(g_S);

    const float scale = 1.0f / sqrtf((float)SEQ);

    // [0] conversions
    convert_all<<<dim3(1024, 2), 256>>>(x, w, xh, xl, Wh, Wl);

    // [1] projections Q1,K1,Q2,K2 = X @ W_z^T  (one batched launch, z=0..3)
    run_hgemm(xh, xl, 0, 0, Wh, Wl, 0, SEQ,
              MROWS / 128, 4, 1, nullptr, PRh, PRl, NTOT, 1.0f);

    // [2] Vt[h] = Wv @ X[h]^T   (z = head)
    run_hgemm(Wh + 4 * SSZ, Wl + 4 * SSZ, 0, 0, xh, xl, 0, SEQ,
              SEQ / 128, NH, 1, nullptr, Vth, Vtl, SSZ, 1.0f);

    // [3] logits: S[i][h] = scale * Q_i[h] @ K_i[h]^T   (z = i*8+h, 16 batches)
    //     Q_i rows at zi*2*MROWS + zr*SEQ inside PR; K_i same with +MROWS base.
    run_hgemm(PRh, PRl, 2 * MROWS, SEQ,
              PRh + NTOT, PRl + NTOT, 2 * MROWS, SEQ,
              SEQ / 128, 2 * NH, 0, S, nullptr, nullptr, SSZ, scale);

    // [4] softmax rows (both attn maps in one launch) -> bf16 pairs
    softmax_pair<<<2 * MROWS, 256>>>(S, Ahh, All);

    // [5] scores: Sc_i = A_i @ W_{5+i}^T -> fp32 (reuse S; z = i*8+h)
    run_hgemm(Ahh, All, MROWS, SEQ,
              Wh + 5 * SSZ, Wl + 5 * SSZ, SEQ, 0,
              SEQ / 128, 2 * NH, 0, S, nullptr, nullptr, SSZ, 1.0f);

    // [6] circle = (Sc1 - Sc2)^2 -> bf16 pair
    diffsq_pair<<<2048, 256>>>(S, S + NTOT, Chh, Cll, NTOT);

    // [7] out[h] = circle[h] @ Vt[h]^T -> fp32
    run_hgemm(Chh, Cll, 0, SEQ, Vth, Vtl, 0, SEQ,
              SEQ / 128, NH, 0, out, nullptr, nullptr, SSZ, 1.0f);
}

// round 8
// speedup vs baseline: 1.9244x; 1.1600x over previous
#include <cuda_runtime.h>
#include <cuda_bf16.h>
#include <math.h>
#include <stdint.h>
#include <stddef.h>

// ============================================================================
// biSoftmax on GB300 via HMMA (mma.sync bf16) split-precision GEMMs.
// R8: algebraic restructure  S_i = X (Wq_i^T Wk_i) X^T  -- replaces Q/K
//     projections + QK^T (24 units/branch) with N_i (1) + T_i (8) + S_i (8).
//     Total GEMM work 80 -> 66 units. Also: prefetch issued right after
//     __syncthreads so cp.async overlaps the whole MMA body.
// All GEMMs are NT: C[m,n] = alpha * sum_k A[m,k] * B[n,k]
// fp32 operands stored as bf16 (hi,lo); accumulate Ahi*Bhi + Ahi*Blo + Alo*Bhi.
// ============================================================================

#define SEQ 2048
#define NH 8
#define MROWS (NH * SEQ)                 // 16384
#define SSZ ((size_t)SEQ * SEQ)          // 2^22
#define NTOT ((size_t)MROWS * SEQ)       // 2^25

typedef __nv_bfloat16 bf16;

// ---------------- scratch (device globals, allocation-free) ----------------
__device__ bf16 g_xh[NTOT],       g_xl[NTOT];
__device__ bf16 g_Wh[3 * SSZ],    g_Wl[3 * SSZ];     // Wv, W1, W2
__device__ bf16 g_WTqh[2 * SSZ],  g_WTql[2 * SSZ];   // Wq1^T, Wq2^T
__device__ bf16 g_WTkh[2 * SSZ],  g_WTkl[2 * SSZ];   // Wk1^T, Wk2^T
__device__ bf16 g_Nh[2 * SSZ],    g_Nl[2 * SSZ];     // N_i = Wk_i^T Wq_i
__device__ bf16 g_Th[2 * NTOT],   g_Tl[2 * NTOT];    // T_i = X N_i^T
__device__ bf16 g_Vth[NTOT],      g_Vtl[NTOT];       // [h][e][t]
__device__ bf16 g_Ah[2 * NTOT],   g_Al[2 * NTOT];    // softmax outputs
__device__ bf16 g_Ch[NTOT],       g_Cl[NTOT];        // circle
__device__ float g_S[2 * NTOT];                      // logits / scores (fp32)

// ---------------- PTX helpers ----------------
__device__ __forceinline__ uint32_t smem_u32(const void* p) {
    uint32_t a;
    asm("{ .reg .u64 t; cvta.to.shared.u64 t, %1; cvt.u32.u64 %0, t; }" : "=r"(a) : "l"(p));
    return a;
}

#define CP16(dst, src) \
    asm volatile("cp.async.cg.shared.global [%0], [%1], 16;" :: "r"(dst), "l"(src) : "memory")
#define CP_COMMIT() asm volatile("cp.async.commit_group;" ::: "memory")
#define CP_WAIT1()  asm volatile("cp.async.wait_group 1;" ::: "memory")

#define LDSM4(r0, r1, r2, r3, a) \
    asm volatile("ldmatrix.sync.aligned.m8n8.x4.shared.b16 {%0,%1,%2,%3}, [%4];" \
        : "=r"(r0), "=r"(r1), "=r"(r2), "=r"(r3) : "r"(a))

#define MMA_BF16(d, a, b) \
    asm volatile("mma.sync.aligned.m16n8k16.row.col.f32.bf16.bf16.f32 " \
        "{%0,%1,%2,%3}, {%4,%5,%6,%7}, {%8,%9}, {%0,%1,%2,%3};" \
        : "+f"((d)[0]), "+f"((d)[1]), "+f"((d)[2]), "+f"((d)[3]) \
        : "r"((a)[0]), "r"((a)[1]), "r"((a)[2]), "r"((a)[3]), "r"((b)[0]), "r"((b)[1]))

// ---------------- HMMA split-precision GEMM ----------------
// CTA tile 128x128, BK=32, 3 stages, 256 threads (8 warps of 64x32), 2 CTAs/SM.
// smem row = 32 bf16 = 64B packed; chunk c of row r stored at
//   r*64 + ((c ^ ((r>>1)&3)) << 4)   -> conflict-free ldmatrix.
// Stage layout: Ahi[0,8192) Alo[8192,16384) Bhi[16384,24576) Blo[24576,32768)
static constexpr int STAGE_B = 32768;
static constexpr int SMEM_HG = 3 * STAGE_B;   // 98304 -> 2 CTAs/SM (192KB)

// z decomposition: zi = z>>3, zr = z&7; row offsets = zi*Hi + zr*Lo
// EPI: 0 = fp32 * alpha, 1 = bf16 (hi,lo) pair
template <int EPI>
__global__ __launch_bounds__(256, 2)
void hgemm3(const bf16* __restrict__ Ah, const bf16* __restrict__ Al,
            const bf16* __restrict__ Bh, const bf16* __restrict__ Bl,
            float* __restrict__ Cf, bf16* __restrict__ Ch, bf16* __restrict__ Cl,
            int K, int ldc, size_t sC,
            int azHi, int azLo, int bzHi, int bzLo, float alpha)
{
    extern __shared__ char smem[];
    const uint32_t sbase = smem_u32(smem);
    const int tid  = threadIdx.x;
    const int lane = tid & 31;
    const int wid  = tid >> 5;
    const int wm   = wid >> 2;          // 0..1 -> 64-row slab
    const int wn   = wid & 3;           // 0..3 -> 32-col slab
    const int row0 = blockIdx.y * 128;
    const int col0 = blockIdx.x * 128;
    const int z    = blockIdx.z;
    const int zi   = z >> 3, zr = z & 7;
    const int aoff = zi * azHi + zr * azLo;
    const int boff = zi * bzHi + zr * bzLo;

    // ---- loader lanes: 256 threads, each 2x16B per buffer per stage ----
    const int lr  = tid >> 1;           // 0..127 row
    const int lcb = (tid & 1) * 2;      // chunk 0 or 2
    const size_t arow = (size_t)(row0 + aoff + lr);
    const size_t brow = (size_t)(col0 + boff + lr);
    const bf16* pAh = Ah + arow * K + lcb * 8;
    const bf16* pAl = Al + arow * K + lcb * 8;
    const bf16* pBh = Bh + brow * K + lcb * 8;
    const bf16* pBl = Bl + brow * K + lcb * 8;
    const uint32_t lsw = (uint32_t)((lr >> 1) & 3);
    const uint32_t st1 = lr * 64 + (((uint32_t)lcb ^ lsw) << 4);
    const uint32_t st2 = lr * 64 + ((((uint32_t)lcb + 1u) ^ lsw) << 4);

    auto prefetch = [&](int go, int stage) {
        const uint32_t sb = sbase + (uint32_t)stage * STAGE_B;
        CP16(sb +          st1, pAh + go); CP16(sb +          st2, pAh + go + 8);
        CP16(sb +  8192u + st1, pAl + go); CP16(sb +  8192u + st2, pAl + go + 8);
        CP16(sb + 16384u + st1, pBh + go); CP16(sb + 16384u + st2, pBh + go + 8);
        CP16(sb + 24576u + st1, pBl + go); CP16(sb + 24576u + st2, pBl + go + 8);
    };

    // ---- fragment addressing ----
    const int lr16  = lane & 15;
    const uint32_t khalf = (uint32_t)(lane >> 4);
    const uint32_t fsw   = (uint32_t)((lr16 >> 1) & 3);
    uint32_t a_base[4], b_base[2];
    #pragma unroll
    for (int mi = 0; mi < 4; mi++) a_base[mi] = (uint32_t)(wm * 64 + mi * 16 + lr16) * 64u;
    #pragma unroll
    for (int g = 0; g < 2; g++)    b_base[g]  = (uint32_t)(wn * 32 + g * 16 + lr16) * 64u;

    float acc[4][4][4];
    #pragma unroll
    for (int mi = 0; mi < 4; mi++)
        #pragma unroll
        for (int nj = 0; nj < 4; nj++)
            #pragma unroll
            for (int q = 0; q < 4; q++) acc[mi][nj][q] = 0.0f;

    const int nk = K >> 5;

    prefetch(0, 0);  CP_COMMIT();
    prefetch(32, 1); CP_COMMIT();

    int cs = 0;           // compute stage
    int ps = 2;           // prefetch stage
    int gof = 64;         // next global k-offset to fetch
    for (int kt = 0; kt < nk; kt++) {
        CP_WAIT1();
        __syncthreads();

        // prefetch overlaps the whole MMA body; stage ps == (kt+2)%3 is free
        // (all warps finished reading it before the sync above).
        if (kt + 2 < nk) { prefetch(gof, ps); gof += 32; }
        CP_COMMIT();

        const uint32_t stg = sbase + (uint32_t)cs * STAGE_B;
        #pragma unroll
        for (int ks = 0; ks < 2; ks++) {
            const uint32_t coff = ((((uint32_t)(ks * 2) + khalf) ^ fsw) << 4);
            uint32_t Bhi[4][2], Blo[4][2];
            #pragma unroll
            for (int g = 0; g < 2; g++) {
                uint32_t q0, q1, q2, q3;
                LDSM4(q0, q1, q2, q3, stg + 16384u + b_base[g] + coff);
                Bhi[2 * g][0] = q0;     Bhi[2 * g][1] = q2;
                Bhi[2 * g + 1][0] = q1; Bhi[2 * g + 1][1] = q3;
                LDSM4(q0, q1, q2, q3, stg + 24576u + b_base[g] + coff);
                Blo[2 * g][0] = q0;     Blo[2 * g][1] = q2;
                Blo[2 * g + 1][0] = q1; Blo[2 * g + 1][1] = q3;
            }
            #pragma unroll
            for (int mi = 0; mi < 4; mi++) {
                uint32_t Ahi[4], Alo[4];
                LDSM4(Ahi[0], Ahi[1], Ahi[2], Ahi[3], stg + a_base[mi] + coff);
                LDSM4(Alo[0], Alo[1], Alo[2], Alo[3], stg + 8192u + a_base[mi] + coff);
                #pragma unroll
                for (int nj = 0; nj < 4; nj++) MMA_BF16(acc[mi][nj], Ahi, Bhi[nj]);
                #pragma unroll
                for (int nj = 0; nj < 4; nj++) MMA_BF16(acc[mi][nj], Ahi, Blo[nj]);
                #pragma unroll
                for (int nj = 0; nj < 4; nj++) MMA_BF16(acc[mi][nj], Alo, Bhi[nj]);
            }
        }

        cs = (cs == 2) ? 0 : cs + 1;
        ps = (ps == 2) ? 0 : ps + 1;
    }

    // ---- epilogue ----
    const size_t cb = (size_t)z * sC;
    #pragma unroll
    for (int mi = 0; mi < 4; mi++) {
        #pragma unroll
        for (int nj = 0; nj < 4; nj++) {
            const int rg = row0 + wm * 64 + mi * 16 + (lane >> 2);
            const int cg = col0 + wn * 32 + nj * 8 + (lane & 3) * 2;
            float d0 = acc[mi][nj][0] * alpha, d1 = acc[mi][nj][1] * alpha;
            float d2 = acc[mi][nj][2] * alpha, d3 = acc[mi][nj][3] * alpha;
            const size_t i0 = cb + (size_t)rg * ldc + cg;
            const size_t i1 = cb + (size_t)(rg + 8) * ldc + cg;
            if (EPI == 0) {
                *(float2*)(Cf + i0) = make_float2(d0, d1);
                *(float2*)(Cf + i1) = make_float2(d2, d3);
            } else {
                __nv_bfloat162 h, l;
                h.x = __float2bfloat16(d0);
                h.y = __float2bfloat16(d1);
                l.x = __float2bfloat16(d0 - __bfloat162float(h.x));
                l.y = __float2bfloat16(d1 - __bfloat162float(h.y));
                *(__nv_bfloat162*)(Ch + i0) = h;
                *(__nv_bfloat162*)(Cl + i0) = l;
                h.x = __float2bfloat16(d2);
                h.y = __float2bfloat16(d3);
                l.x = __float2bfloat16(d2 - __bfloat162float(h.x));
                l.y = __float2bfloat16(d3 - __bfloat162float(h.y));
                *(__nv_bfloat162*)(Ch + i1) = h;
                *(__nv_bfloat162*)(Cl + i1) = l;
            }
        }
    }
}

// ---------------- conversions ----------------
struct WPtrs3 { const float* p[3]; };   // Wv, W1, W2
struct WPtrs4 { const float* p[4]; };   // Wq1, Wk1, Wq2, Wk2

__global__ __launch_bounds__(256)
void convert_all(const float* __restrict__ x, WPtrs3 w,
                 bf16* __restrict__ xh, bf16* __restrict__ xl,
                 bf16* __restrict__ Wh, bf16* __restrict__ Wl)
{
    const size_t stride = (size_t)gridDim.x * blockDim.x;
    size_t i = (size_t)blockIdx.x * blockDim.x + threadIdx.x;
    if (blockIdx.y == 0) {
        for (; i < NTOT; i += stride) {
            float f = x[i];
            bf16 h = __float2bfloat16(f);
            xh[i] = h;
            xl[i] = __float2bfloat16(f - __bfloat162float(h));
        }
    } else {
        const size_t n = 3 * SSZ;
        for (; i < n; i += stride) {
            const int r = (int)(i >> 22);            // SSZ = 2^22
            const size_t off = i & (SSZ - 1);
            float f = w.p[r][off];
            bf16 h = __float2bfloat16(f);
            Wh[i] = h;
            Wl[i] = __float2bfloat16(f - __bfloat162float(h));
        }
    }
}

// Transpose Wq1,Wk1,Wq2,Wk2 (fp32 [SEQ,SEQ]) -> bf16 (hi,lo) pairs.
// z=0 -> Wq1 -> WTq+0 ; z=1 -> Wk1 -> WTk+0 ; z=2 -> Wq2 -> WTq+SSZ ; z=3 -> Wk2 -> WTk+SSZ
__global__ __launch_bounds__(256)
void transpose_pairs(WPtrs4 w,
                     bf16* __restrict__ WTqh, bf16* __restrict__ WTql,
                     bf16* __restrict__ WTkh, bf16* __restrict__ WTkl)
{
    __shared__ float t[32][33];
    const int z = blockIdx.z;
    const float* src = w.p[z];
    bf16* dh = (z & 1) ? WTkh : WTqh;
    bf16* dl = (z & 1) ? WTkl : WTql;
    const size_t base = (z >> 1) ? SSZ : 0;

    const int tx = threadIdx.x, ty = threadIdx.y;   // 32 x 8
    const int x = blockIdx.x * 32 + tx;
    const int y = blockIdx.y * 32 + ty;
    #pragma unroll
    for (int r = 0; r < 4; r++)
        t[ty + r * 8][tx] = src[(size_t)(y + r * 8) * SEQ + x];
    __syncthreads();
    const int x2 = blockIdx.y * 32 + tx;
    const int y2 = blockIdx.x * 32 + ty;
    #pragma unroll
    for (int r = 0; r < 4; r++) {
        float f = t[tx][ty + r * 8];
        bf16 h = __float2bfloat16(f);
        const size_t idx = base + (size_t)(y2 + r * 8) * SEQ + x2;
        dh[idx] = h;
        dl[idx] = __float2bfloat16(f - __bfloat162float(h));
    }
}

__global__ __launch_bounds__(256)
void softmax_pair(const float* __restrict__ S, bf16* __restrict__ Ph,
                  bf16* __restrict__ Pl)
{
    const int tid = threadIdx.x;
    const float* p = S + (size_t)blockIdx.x * SEQ;
    bf16* oh = Ph + (size_t)blockIdx.x * SEQ;
    bf16* ol = Pl + (size_t)blockIdx.x * SEQ;
    __shared__ float buf[SEQ];
    __shared__ float red[256];

    float m = -INFINITY;
    for (int i = tid; i < SEQ; i += 256) { float v = p[i]; buf[i] = v; m = fmaxf(m, v); }
    red[tid] = m; __syncthreads();
    for (int s = 128; s > 0; s >>= 1) { if (tid < s) red[tid] = fmaxf(red[tid], red[tid + s]); __syncthreads(); }
    m = red[0]; __syncthreads();

    float sum = 0.0f;
    for (int i = tid; i < SEQ; i += 256) { float e = __expf(buf[i] - m); buf[i] = e; sum += e; }
    red[tid] = sum; __syncthreads();
    for (int s = 128; s > 0; s >>= 1) { if (tid < s) red[tid] += red[tid + s]; __syncthreads(); }
    const float inv = 1.0f / red[0]; __syncthreads();

    for (int i = tid; i < SEQ; i += 256) {
        float f = buf[i] * inv;
        bf16 h = __float2bfloat16(f);
        oh[i] = h;
        ol[i] = __float2bfloat16(f - __bfloat162float(h));
    }
}

__global__ __launch_bounds__(256)
void diffsq_pair(const float* __restrict__ a, const float* __restrict__ b,
                 bf16* __restrict__ hi, bf16* __restrict__ lo, size_t n)
{
    size_t i = (size_t)blockIdx.x * blockDim.x + threadIdx.x;
    size_t st = (size_t)gridDim.x * blockDim.x;
    for (; i < n; i += st) {
        float d = a[i] - b[i];
        float f = d * d;
        bf16 h = __float2bfloat16(f);
        hi[i] = h;
        lo[i] = __float2bfloat16(f - __bfloat162float(h));
    }
}

// ---------------- host side ----------------
template <typename T>
static T* sym_addr(T* symbol) {
    void* p = nullptr;
    cudaGetSymbolAddress(&p, (const void*)symbol);
    return (T*)p;
}

static void run_hgemm(const bf16* Ah, const bf16* Al, int azHi, int azLo,
                      const bf16* Bh, const bf16* Bl, int bzHi, int bzLo,
                      int Mtiles, int batch, int epi,
                      float* Cf, bf16* Ch, bf16* Cl, size_t sC, float alpha)
{
    dim3 grid(SEQ / 128, Mtiles, batch);
    if (epi == 0)
        hgemm3<0><<<grid, 256, SMEM_HG>>>(Ah, Al, Bh, Bl, Cf, Ch, Cl,
                                          SEQ, SEQ, sC, azHi, azLo, bzHi, bzLo, alpha);
    else
        hgemm3<1><<<grid, 256, SMEM_HG>>>(Ah, Al, Bh, Bl, Cf, Ch, Cl,
                                          SEQ, SEQ, sC, azHi, azLo, bzHi, bzLo, alpha);
}

extern "C" void kernel_launch(void* const* d_in, const int* in_sizes, int n_in,
                              void* d_out, int out_size)
{
    (void)in_sizes; (void)n_in; (void)out_size;
    const float* x = (const float*)d_in[0];
    WPtrs4 wqk;
    wqk.p[0] = (const float*)d_in[1];   // Wq1
    wqk.p[1] = (const float*)d_in[2];   // Wk1
    wqk.p[2] = (const float*)d_in[3];   // Wq2
    wqk.p[3] = (const float*)d_in[4];   // Wk2
    WPtrs3 wv;
    wv.p[0] = (const float*)d_in[5];    // Wv
    wv.p[1] = (const float*)d_in[6];    // W1
    wv.p[2] = (const float*)d_in[7];    // W2
    float* out = (float*)d_out;

    cudaFuncSetAttribute((const void*)hgemm3<0>,
                         cudaFuncAttributeMaxDynamicSharedMemorySize, SMEM_HG);
    cudaFuncSetAttribute((const void*)hgemm3<1>,
                         cudaFuncAttributeMaxDynamicSharedMemorySize, SMEM_HG);

    bf16 *xh = sym_addr(g_xh),   *xl = sym_addr(g_xl);
    bf16 *Wh = sym_addr(g_Wh),   *Wl = sym_addr(g_Wl);
    bf16 *WTqh = sym_addr(g_WTqh), *WTql = sym_addr(g_WTql);
    bf16 *WTkh = sym_addr(g_WTkh), *WTkl = sym_addr(g_WTkl);
    bf16 *Nhh = sym_addr(g_Nh),  *Nll = sym_addr(g_Nl);
    bf16 *Thh = sym_addr(g_Th),  *Tll = sym_addr(g_Tl);
    bf16 *Vth = sym_addr(g_Vth), *Vtl = sym_addr(g_Vtl);
    bf16 *Ahh = sym_addr(g_Ah),  *All = sym_addr(g_Al);
    bf16 *Chh = sym_addr(g_Ch),  *Cll = sym_addr(g_Cl);
    float *S = sym_addr(g_S);

    const float scale = 1.0f / sqrtf((float)SEQ);

    // [0] conversions: x and {Wv, W1, W2}
    convert_all<<<dim3(1024, 2), 256>>>(x, wv, xh, xl, Wh, Wl);

    // [1] transposes: Wq1,Wk1,Wq2,Wk2 -> WTq/WTk bf16 pairs
    transpose_pairs<<<dim3(SEQ / 32, SEQ / 32, 4), dim3(32, 8)>>>(
        wqk, WTqh, WTql, WTkh, WTkl);

    // [2] N_i = Wk_i^T Wq_i = WTk_i @ WTq_i^T   (z = i, 2 batches)
    run_hgemm(WTkh, WTkl, 0, SEQ, WTqh, WTql, 0, SEQ,
              SEQ / 128, 2, 1, nullptr, Nhh, Nll, SSZ, 1.0f);

    // [3] T_i = X @ N_i^T   (z = i, full M = 16384)
    run_hgemm(xh, xl, 0, 0, Nhh, Nll, 0, SEQ,
              MROWS / 128, 2, 1, nullptr, Thh, Tll, NTOT, 1.0f);

    // [4] Vt[h] = Wv @ X[h]^T   (z = head)
    run_hgemm(Wh, Wl, 0, 0, xh, xl, 0, SEQ,
              SEQ / 128, NH, 1, nullptr, Vth, Vtl, SSZ, 1.0f);

    // [5] logits: S[i][h] = scale * T_i[h] @ X[h]^T   (z = i*8+h, 16 batches)
    run_hgemm(Thh, Tll, MROWS, SEQ, xh, xl, 0, SEQ,
              SEQ / 128, 2 * NH, 0, S, nullptr, nullptr, SSZ, scale);

    // [6] softmax rows (both attn maps) -> bf16 pairs
    softmax_pair<<<2 * MROWS, 256>>>(S, Ahh, All);

    // [7] scores: Sc_i = A_i @ W_{1+i}^T -> fp32 (reuse S; z = i*8+h)
    run_hgemm(Ahh, All, MROWS, SEQ, Wh + SSZ, Wl + SSZ, SSZ ? SEQ : SEQ, 0,
              SEQ / 128, 2 * NH, 0, S, nullptr, nullptr, SSZ, 1.0f);

    // [8] circle = (Sc1 - Sc2)^2 -> bf16 pair
    diffsq_pair<<<2048, 256>>>(S, S + NTOT, Chh, Cll, NTOT);

    // [9] out[h] = circle[h] @ Vt[h]^T -> fp32
    run_hgemm(Chh, Cll, 0, SEQ, Vth, Vtl, 0, SEQ,
              SEQ / 128, NH, 0, out, nullptr, nullptr, SSZ, 1.0f);
}